// round 11
// baseline (speedup 1.0000x reference)
#include <cuda_runtime.h>
#include <cuda_fp16.h>
#include <cstdint>

#define BATCH 4096
#define MCOLS 4096
#define NROWS 4096
#define NNZ_PER_ROW 819
#define NNZ_TOTAL (NROWS * NNZ_PER_ROW)

#define BM 128
#define BN 128
#define BK 64
#define KSTEPS (MCOLS / BK)        // 64
#define NSTAGES 3
#define SROWH 72                   // halves per row (144B); LDSM phases tile all 32 banks
#define TILE_HALVES (128 * SROWH)  // 9216 halves (18KB) per matrix per stage
#define STAGE_HALVES (2 * TILE_HALVES)            // A+B per stage (36KB)
#define SMEM_BYTES (NSTAGES * STAGE_HALVES * 2)   // 110592 B -> 2 CTAs/SM

#define XCHUNKS (BATCH * MCOLS / 4)   // float4 chunks of x

// fp16 operand buffers. g_Wh is zero-initialized at module load (0 bits = +0.0h);
// the prep kernel writes the same values to the same (fixed CSR) positions every
// call -> deterministic across graph replays.
__device__ __half g_Wh[(size_t)NROWS * MCOLS];
__device__ __half g_Xh[(size_t)BATCH * MCOLS];

__global__ void __launch_bounds__(256)
prep_kernel(const float* __restrict__ x, const float* __restrict__ val,
            const int* __restrict__ rows, const int* __restrict__ cols) {
    int i = blockIdx.x * blockDim.x + threadIdx.x;
    if (i < XCHUNKS) {
        size_t o = (size_t)i * 4;
        float4 v = *(const float4*)(x + o);
        __half2 h0 = __floats2half2_rn(v.x, v.y);
        __half2 h1 = __floats2half2_rn(v.z, v.w);
        uint2 p;
        p.x = *(const uint32_t*)&h0;
        p.y = *(const uint32_t*)&h1;
        *(uint2*)(g_Xh + o) = p;
    } else {
        int j = i - XCHUNKS;
        if (j < NNZ_TOTAL) {
            g_Wh[(size_t)rows[j] * MCOLS + cols[j]] = __float2half_rn(val[j]);
        }
    }
}

__device__ __forceinline__ void cp16(uint32_t dst, const void* src) {
    asm volatile("cp.async.cg.shared.global [%0], [%1], 16;\n" :: "r"(dst), "l"(src));
}

// Each thread owns one row (tid>>1) and a 64B half-row ((tid&1)*32 halves):
// 4 x 16B chunks per matrix, 8 cp.async total per stage.
__device__ __forceinline__ void load_stage(uint32_t sAt, uint32_t sBt,
                                           const __half* __restrict__ gA,
                                           const __half* __restrict__ gB) {
    #pragma unroll
    for (int i = 0; i < 4; ++i) {
        uint32_t so = (uint32_t)(i * 8) * 2;   // +8 halves (16B) per chunk
        cp16(sAt + so, gA + i * 8);
        cp16(sBt + so, gB + i * 8);
    }
    asm volatile("cp.async.commit_group;\n" ::);
}

#define MMA(d, a0, a1, a2, a3, b0, b1)                                      \
    asm volatile(                                                           \
        "mma.sync.aligned.m16n8k16.row.col.f32.f16.f16.f32 "                \
        "{%0,%1,%2,%3}, {%4,%5,%6,%7}, {%8,%9}, {%0,%1,%2,%3};"             \
        : "+f"((d)[0]), "+f"((d)[1]), "+f"((d)[2]), "+f"((d)[3])            \
        : "r"(a0), "r"(a1), "r"(a2), "r"(a3), "r"(b0), "r"(b1))

#define LDSM4(r0, r1, r2, r3, addr)                                         \
    asm volatile("ldmatrix.sync.aligned.m8n8.x4.shared.b16 "                \
                 "{%0,%1,%2,%3}, [%4];"                                     \
                 : "=r"(r0), "=r"(r1), "=r"(r2), "=r"(r3) : "r"(addr))

// ldmatrix fragment loads for one k16 step (same lane mapping as R10).
__device__ __forceinline__ void load_frags(uint32_t af[2][4], uint32_t bf[8][2],
                                           uint32_t aAddr, uint32_t bAddr, int ks) {
    #pragma unroll
    for (int mt = 0; mt < 2; ++mt)
        LDSM4(af[mt][0], af[mt][1], af[mt][2], af[mt][3],
              aAddr + (uint32_t)((mt * 16 * SROWH + ks * 16) * 2));
    #pragma unroll
    for (int ntp = 0; ntp < 4; ++ntp)
        LDSM4(bf[2 * ntp][0], bf[2 * ntp][1], bf[2 * ntp + 1][0], bf[2 * ntp + 1][1],
              bAddr + (uint32_t)((ntp * 16 * SROWH + ks * 16) * 2));
}

__global__ void __launch_bounds__(256, 2)
sgemm_fp16(const float* __restrict__ bias, float* __restrict__ out) {
    extern __shared__ __half smem[];

    const int tid  = threadIdx.x;
    const int lane = tid & 31;
    const int warp = tid >> 5;
    const int wm = (warp & 3) * 32;     // 4 warps in M
    const int wn = (warp >> 2) * 64;    // 2 warps in N
    const int qr = lane >> 2;
    const int tg = lane & 3;

    const int m0 = blockIdx.y * BM;
    const int n0 = blockIdx.x * BN;

    float acc[2][8][4];
    #pragma unroll
    for (int i = 0; i < 2; i++)
        #pragma unroll
        for (int j = 0; j < 8; j++)
            #pragma unroll
            for (int c = 0; c < 4; c++) acc[i][j][c] = 0.f;

    const uint32_t sbase = (uint32_t)__cvta_generic_to_shared(smem);

    // ldmatrix per-lane source addresses (stage 0; stage offset added in-loop)
    const int lrA = wm + (lane & 7) + ((lane >> 3) & 1) * 8;
    const int lkA = (lane >> 4) * 8;
    const int lrB = wn + (lane & 7) + (lane >> 4) * 8;
    const int lkB = ((lane >> 3) & 1) * 8;
    const uint32_t aFrag0 = sbase + (uint32_t)((lrA * SROWH + lkA) * 2);
    const uint32_t bFrag0 = sbase + (uint32_t)(TILE_HALVES * 2)
                                  + (uint32_t)((lrB * SROWH + lkB) * 2);

    // loader thread's fixed (row, 64B half-row)
    const int lrow = tid >> 1;          // 0..127
    const int lcol = (tid & 1) * 32;    // halves
    const uint32_t lA = sbase + (uint32_t)(lrow * SROWH + lcol) * 2;
    const uint32_t lB = lA + (uint32_t)(TILE_HALVES * 2);
    const __half* gA = g_Xh + (size_t)(m0 + lrow) * MCOLS + lcol;
    const __half* gB = g_Wh + (size_t)(n0 + lrow) * MCOLS + lcol;

    // prologue: stages 0 and 1 into buffers 0 and 1
    load_stage(lA, lB, gA, gB);
    load_stage(lA + STAGE_HALVES * 2, lB + STAGE_HALVES * 2, gA + BK, gB + BK);

    int cur = 0;   // buffer holding stage kt
    for (int kt = 0; kt < KSTEPS; ++kt) {
        if (kt + 2 < KSTEPS) {
            const int lb = (cur + 2 >= NSTAGES) ? cur - 1 : cur + 2;
            load_stage(lA + (uint32_t)(lb * STAGE_HALVES * 2),
                       lB + (uint32_t)(lb * STAGE_HALVES * 2),
                       gA + (size_t)(kt + 2) * BK, gB + (size_t)(kt + 2) * BK);
            asm volatile("cp.async.wait_group 2;\n" ::);
        } else if (kt + 1 < KSTEPS) {
            asm volatile("cp.async.wait_group 1;\n" ::);
        } else {
            asm volatile("cp.async.wait_group 0;\n" ::);
        }
        __syncthreads();   // collective completion of stage kt

        const uint32_t aAddr = aFrag0 + (uint32_t)(cur * STAGE_HALVES * 2);
        const uint32_t bAddr = bFrag0 + (uint32_t)(cur * STAGE_HALVES * 2);

        // Cross-ks fragment pipeline over 4 k16 steps.
        uint32_t af[2][2][4];
        uint32_t bf[2][8][2];
        load_frags(af[0], bf[0], aAddr, bAddr, 0);

        #pragma unroll
        for (int ks = 0; ks < 4; ++ks) {
            const int c = ks & 1;
            if (ks < 3)
                load_frags(af[c ^ 1], bf[c ^ 1], aAddr, bAddr, ks + 1);
            #pragma unroll
            for (int mt = 0; mt < 2; ++mt)
                #pragma unroll
                for (int nt = 0; nt < 8; ++nt)
                    MMA(acc[mt][nt], af[c][mt][0], af[c][mt][1],
                        af[c][mt][2], af[c][mt][3],
                        bf[c][nt][0], bf[c][nt][1]);
        }
        __syncthreads();   // gate buffer reuse by next iteration's prefetch

        cur = (cur == NSTAGES - 1) ? 0 : cur + 1;
    }

    // Epilogue
    #pragma unroll
    for (int mt = 0; mt < 2; ++mt) {
        const int rbase = m0 + wm + mt * 16 + qr;
        #pragma unroll
        for (int nt = 0; nt < 8; ++nt) {
            const int nbase = n0 + wn + nt * 8 + 2 * tg;
            const float b0 = bias[nbase];
            const float b1 = bias[nbase + 1];
            float2 v0 = make_float2(acc[mt][nt][0] + b0, acc[mt][nt][1] + b1);
            float2 v1 = make_float2(acc[mt][nt][2] + b0, acc[mt][nt][3] + b1);
            *(float2*)(out + (size_t)rbase * NROWS + nbase) = v0;
            *(float2*)(out + (size_t)(rbase + 8) * NROWS + nbase) = v1;
        }
    }
}

extern "C" void kernel_launch(void* const* d_in, const int* in_sizes, int n_in,
                              void* d_out, int out_size) {
    const float* x    = (const float*)d_in[0];
    const float* wval = (const float*)d_in[1];
    const float* bias = (const float*)d_in[2];
    const int*   rows = (const int*)d_in[3];
    const int*   cols = (const int*)d_in[4];
    float* out = (float*)d_out;

    prep_kernel<<<(XCHUNKS + NNZ_TOTAL + 255) / 256, 256>>>(x, wval, rows, cols);

    cudaFuncSetAttribute(sgemm_fp16,
                         cudaFuncAttributeMaxDynamicSharedMemorySize, SMEM_BYTES);
    dim3 grid(NROWS / BN, BATCH / BM);
    sgemm_fp16<<<grid, 256, SMEM_BYTES>>>(bias, out);
}

// round 12
// speedup vs baseline: 1.3210x; 1.3210x over previous
#include <cuda_runtime.h>
#include <cuda_fp16.h>
#include <cstdint>

#define BATCH 4096
#define MCOLS 4096
#define NROWS 4096
#define NNZ_PER_ROW 819
#define NNZ_TOTAL (NROWS * NNZ_PER_ROW)

#define BM 128
#define BN 128
#define BK 32
#define KSTEPS (MCOLS / BK)        // 128
#define NSTAGES 4
#define SROWH 40                   // halves per row (80B); LDSM phases tile all 32 banks
#define TILE_HALVES (128 * SROWH)  // 10KB per matrix per stage
#define STAGE_HALVES (2 * TILE_HALVES)            // A+B per stage (20KB)
#define SMEM_BYTES (NSTAGES * STAGE_HALVES * 2)   // 81920 B -> 2 CTAs/SM

#define XCHUNKS (BATCH * MCOLS / 4)   // float4 chunks of x

// fp16 operand buffers. g_Wh is zero-initialized at module load (0 bits = +0.0h);
// the prep kernel writes the same values to the same (fixed CSR) positions every
// call -> deterministic across graph replays.
__device__ __half g_Wh[(size_t)NROWS * MCOLS];
__device__ __half g_Xh[(size_t)BATCH * MCOLS];

__global__ void __launch_bounds__(256)
prep_kernel(const float* __restrict__ x, const float* __restrict__ val,
            const int* __restrict__ rows, const int* __restrict__ cols) {
    int i = blockIdx.x * blockDim.x + threadIdx.x;
    if (i < XCHUNKS) {
        size_t o = (size_t)i * 4;
        float4 v = *(const float4*)(x + o);
        __half2 h0 = __floats2half2_rn(v.x, v.y);
        __half2 h1 = __floats2half2_rn(v.z, v.w);
        uint2 p;
        p.x = *(const uint32_t*)&h0;
        p.y = *(const uint32_t*)&h1;
        *(uint2*)(g_Xh + o) = p;
    } else {
        int j = i - XCHUNKS;
        if (j < NNZ_TOTAL) {
            g_Wh[(size_t)rows[j] * MCOLS + cols[j]] = __float2half_rn(val[j]);
        }
    }
}

__device__ __forceinline__ void cp16(uint32_t dst, const void* src) {
    asm volatile("cp.async.cg.shared.global [%0], [%1], 16;\n" :: "r"(dst), "l"(src));
}

// R10 loader: thread owns (row tid>>2, 16B seg tid&3); 2 chunks per matrix.
__device__ __forceinline__ void load_stage(uint32_t sAt, uint32_t sBt,
                                           const __half* __restrict__ gA,
                                           const __half* __restrict__ gB) {
    #pragma unroll
    for (int i = 0; i < 2; ++i) {
        uint32_t so = (uint32_t)(i * 64 * SROWH) * 2;   // +64 rows per step
        cp16(sAt + so, gA + (size_t)i * 64 * MCOLS);
        cp16(sBt + so, gB + (size_t)i * 64 * MCOLS);
    }
    asm volatile("cp.async.commit_group;\n" ::);
}

#define MMA(d, a0, a1, a2, a3, b0, b1)                                      \
    asm volatile(                                                           \
        "mma.sync.aligned.m16n8k16.row.col.f32.f16.f16.f32 "                \
        "{%0,%1,%2,%3}, {%4,%5,%6,%7}, {%8,%9}, {%0,%1,%2,%3};"             \
        : "+f"((d)[0]), "+f"((d)[1]), "+f"((d)[2]), "+f"((d)[3])            \
        : "r"(a0), "r"(a1), "r"(a2), "r"(a3), "r"(b0), "r"(b1))

#define LDSM4(r0, r1, r2, r3, addr)                                         \
    asm volatile("ldmatrix.sync.aligned.m8n8.x4.shared.b16 "                \
                 "{%0,%1,%2,%3}, [%4];"                                     \
                 : "=r"(r0), "=r"(r1), "=r"(r2), "=r"(r3) : "r"(addr))

// ldmatrix fragment loads (R10 lane mapping).
__device__ __forceinline__ void load_frags(uint32_t af[2][4], uint32_t bf[8][2],
                                           uint32_t aAddr, uint32_t bAddr, int ks) {
    #pragma unroll
    for (int mt = 0; mt < 2; ++mt)
        LDSM4(af[mt][0], af[mt][1], af[mt][2], af[mt][3],
              aAddr + (uint32_t)((mt * 16 * SROWH + ks * 16) * 2));
    #pragma unroll
    for (int ntp = 0; ntp < 4; ++ntp)
        LDSM4(bf[2 * ntp][0], bf[2 * ntp][1], bf[2 * ntp + 1][0], bf[2 * ntp + 1][1],
              bAddr + (uint32_t)((ntp * 16 * SROWH + ks * 16) * 2));
}

__global__ void __launch_bounds__(256, 2)
sgemm_fp16(const float* __restrict__ bias, float* __restrict__ out) {
    extern __shared__ __half smem[];

    const int tid  = threadIdx.x;
    const int lane = tid & 31;
    const int warp = tid >> 5;
    const int wm = (warp & 3) * 32;     // 4 warps in M
    const int wn = (warp >> 2) * 64;    // 2 warps in N
    const int qr = lane >> 2;
    const int tg = lane & 3;

    const int m0 = blockIdx.y * BM;
    const int n0 = blockIdx.x * BN;

    float acc[2][8][4];
    #pragma unroll
    for (int i = 0; i < 2; i++)
        #pragma unroll
        for (int j = 0; j < 8; j++)
            #pragma unroll
            for (int c = 0; c < 4; c++) acc[i][j][c] = 0.f;

    const uint32_t sbase = (uint32_t)__cvta_generic_to_shared(smem);

    // ldmatrix per-lane source addresses (stage 0; stage offset added in-loop)
    const int lrA = wm + (lane & 7) + ((lane >> 3) & 1) * 8;
    const int lkA = (lane >> 4) * 8;
    const int lrB = wn + (lane & 7) + (lane >> 4) * 8;
    const int lkB = ((lane >> 3) & 1) * 8;
    const uint32_t aFrag0 = sbase + (uint32_t)((lrA * SROWH + lkA) * 2);
    const uint32_t bFrag0 = sbase + (uint32_t)(TILE_HALVES * 2)
                                  + (uint32_t)((lrB * SROWH + lkB) * 2);

    // loader thread's fixed (row, seg): 16B chunks
    const int lrow = tid >> 2;          // 0..63
    const int lseg = tid & 3;           // 0..3
    const uint32_t lA = sbase + (uint32_t)(lrow * SROWH + lseg * 8) * 2;
    const uint32_t lB = lA + (uint32_t)(TILE_HALVES * 2);
    const __half* gA = g_Xh + (size_t)(m0 + lrow) * MCOLS + lseg * 8;
    const __half* gB = g_Wh + (size_t)(n0 + lrow) * MCOLS + lseg * 8;

    // prologue: stages 0,1,2 into buffers 0,1,2
    load_stage(lA, lB, gA, gB);
    load_stage(lA + 1 * STAGE_HALVES * 2, lB + 1 * STAGE_HALVES * 2, gA + BK, gB + BK);
    load_stage(lA + 2 * STAGE_HALVES * 2, lB + 2 * STAGE_HALVES * 2,
               gA + 2 * BK, gB + 2 * BK);

    int cur = 0;   // buffer holding stage kt
    for (int kt = 0; kt < KSTEPS; ++kt) {
        // Pending groups here: stages kt+1, kt+2 (when they exist). Allowing 2
        // pending completes stage kt for ALL threads; the barrier then orders
        // those smem writes against every thread's LDSM reads.
        if (kt + 2 < KSTEPS) {
            asm volatile("cp.async.wait_group 2;\n" ::);
        } else if (kt + 1 < KSTEPS) {
            asm volatile("cp.async.wait_group 1;\n" ::);
        } else {
            asm volatile("cp.async.wait_group 0;\n" ::);
        }
        __syncthreads();   // SINGLE barrier per ktile

        const uint32_t aAddr = aFrag0 + (uint32_t)(cur * STAGE_HALVES * 2);
        const uint32_t bAddr = bFrag0 + (uint32_t)(cur * STAGE_HALVES * 2);

        // First fragment loads go before the prefetch so LDSM heads the queue.
        uint32_t af[2][2][4];
        uint32_t bf[2][8][2];
        load_frags(af[0], bf[0], aAddr, bAddr, 0);

        // Prefetch stage kt+3 into buffer (kt+3)%4 == (kt-1)%4: that buffer was
        // last read during iteration kt-1, whose compute finished before the
        // barrier above -> overwrite is safe with a single barrier.
        if (kt + 3 < KSTEPS) {
            const int lb = (kt + 3) & (NSTAGES - 1);
            load_stage(lA + (uint32_t)(lb * STAGE_HALVES * 2),
                       lB + (uint32_t)(lb * STAGE_HALVES * 2),
                       gA + (size_t)(kt + 3) * BK, gB + (size_t)(kt + 3) * BK);
        }

        #pragma unroll
        for (int ks = 0; ks < 2; ++ks) {
            const int c = ks & 1;
            if (ks < 1)
                load_frags(af[c ^ 1], bf[c ^ 1], aAddr, bAddr, ks + 1);
            #pragma unroll
            for (int mt = 0; mt < 2; ++mt)
                #pragma unroll
                for (int nt = 0; nt < 8; ++nt)
                    MMA(acc[mt][nt], af[c][mt][0], af[c][mt][1],
                        af[c][mt][2], af[c][mt][3],
                        bf[c][nt][0], bf[c][nt][1]);
        }

        cur = (cur + 1) & (NSTAGES - 1);
    }

    // Epilogue
    #pragma unroll
    for (int mt = 0; mt < 2; ++mt) {
        const int rbase = m0 + wm + mt * 16 + qr;
        #pragma unroll
        for (int nt = 0; nt < 8; ++nt) {
            const int nbase = n0 + wn + nt * 8 + 2 * tg;
            const float b0 = bias[nbase];
            const float b1 = bias[nbase + 1];
            float2 v0 = make_float2(acc[mt][nt][0] + b0, acc[mt][nt][1] + b1);
            float2 v1 = make_float2(acc[mt][nt][2] + b0, acc[mt][nt][3] + b1);
            *(float2*)(out + (size_t)rbase * NROWS + nbase) = v0;
            *(float2*)(out + (size_t)(rbase + 8) * NROWS + nbase) = v1;
        }
    }
}

extern "C" void kernel_launch(void* const* d_in, const int* in_sizes, int n_in,
                              void* d_out, int out_size) {
    const float* x    = (const float*)d_in[0];
    const float* wval = (const float*)d_in[1];
    const float* bias = (const float*)d_in[2];
    const int*   rows = (const int*)d_in[3];
    const int*   cols = (const int*)d_in[4];
    float* out = (float*)d_out;

    prep_kernel<<<(XCHUNKS + NNZ_TOTAL + 255) / 256, 256>>>(x, wval, rows, cols);

    cudaFuncSetAttribute(sgemm_fp16,
                         cudaFuncAttributeMaxDynamicSharedMemorySize, SMEM_BYTES);
    dim3 grid(NROWS / BN, BATCH / BM);
    sgemm_fp16<<<grid, 256, SMEM_BYTES>>>(bias, out);
}